// round 8
// baseline (speedup 1.0000x reference)
#include <cuda_runtime.h>
#include <math.h>

// Problem constants
#define B_   8
#define LQ_  512
#define T_   8192
#define DIM_ 256
#define H_   8
#define HD_  32

// ---------------------------------------------------------------------------
// Scratch (device globals: allocation-free per harness rules)
// ---------------------------------------------------------------------------
__device__ float g_Q[(size_t)B_ * LQ_ * DIM_];              //  4 MB, [b][q][256]
__device__ float g_K[(size_t)B_ * H_ * T_ * HD_];           // 64 MB, [b][h][t][d]
__device__ float g_V[(size_t)B_ * H_ * T_ * HD_];           // 64 MB, [b][h][t][d]
__device__ float g_mask[(size_t)LQ_ * T_];                  // 16 MB, [q][t]
__device__ float g_att[(size_t)B_ * LQ_ * DIM_];            //  4 MB, [b][q][h*32+d]

// ---------------------------------------------------------------------------
// Mask precompute: mask[q][t] = ms * (rel_bias[clip(dt)] + log(exp(-.5*(dt/64)^2)+1e-6))
// dt = t - q*(T-1)/(Lq-1)
// ---------------------------------------------------------------------------
__global__ void mask_kernel(const float* __restrict__ rel_bias,
                            const float* __restrict__ mask_scale)
{
    int idx = blockIdx.x * 256 + threadIdx.x;   // grid sized exactly LQ_*T_/256
    int q = idx >> 13;          // /8192
    int t = idx & (T_ - 1);
    const float step = 8191.0f / 511.0f;        // linspace step in fp32 (matches jax)
    float tau = (float)q * step;
    float dt = (float)t - tau;
    float dtc = fminf(fmaxf(dt, -128.0f), 128.0f);
    int bi = (int)dtc + 128;                    // trunc-toward-zero matches astype(int32)
    float bias = rel_bias[bi];
    float z = dt * (1.0f / 64.0f);
    float lg = logf(expf(-0.5f * z * z) + 1e-6f);
    g_mask[idx] = mask_scale[0] * (bias + lg);
}

// ---------------------------------------------------------------------------
// Generic fp32 GEMM:  C[m][n] = sum_k A[m][k]*W[n][k] + bias[n],  Kdim = 256
// CTA tile 128x128, 256 threads, 8x8 micro-tile, k-chunk 16.
// mode 0: row-major store into C0 (ld = 256)
// mode 1: KV head-major store: n<256 -> C0 (=K), else C1 (=V);
//         row m = b*8192+t, col (n&255) = h*32+d  ->  [((b*8+h)*8192+t)*32+d]
// ---------------------------------------------------------------------------
__global__ __launch_bounds__(256) void gemm128(
    const float* __restrict__ A, const float* __restrict__ W,
    const float* __restrict__ bias,
    float* __restrict__ C0, float* __restrict__ C1, int mode)
{
    __shared__ float As[16][132];   // [k][m], padded stride 132 (conflict-free)
    __shared__ float Ws[16][132];   // [k][n]

    const int tid = threadIdx.x;
    const int tx = tid & 15;        // n micro-tile index
    const int ty = tid >> 4;        // m micro-tile index
    const int m0 = blockIdx.y << 7;
    const int n0 = blockIdx.x << 7;

    float acc[8][8];
#pragma unroll
    for (int i = 0; i < 8; i++)
#pragma unroll
        for (int j = 0; j < 8; j++) acc[i][j] = 0.f;

    const int lr = tid >> 2;          // 0..63 : tile row for loads
    const int lk = (tid & 3) << 2;    // 0,4,8,12 : k offset (float4)

    for (int kc = 0; kc < 256; kc += 16) {
#pragma unroll
        for (int p = 0; p < 2; p++) {
            int r = lr + (p << 6);
            float4 av = *(const float4*)(A + (size_t)(m0 + r) * DIM_ + kc + lk);
            As[lk + 0][r] = av.x; As[lk + 1][r] = av.y;
            As[lk + 2][r] = av.z; As[lk + 3][r] = av.w;
            float4 wv = *(const float4*)(W + (size_t)(n0 + r) * DIM_ + kc + lk);
            Ws[lk + 0][r] = wv.x; Ws[lk + 1][r] = wv.y;
            Ws[lk + 2][r] = wv.z; Ws[lk + 3][r] = wv.w;
        }
        __syncthreads();
#pragma unroll
        for (int kk = 0; kk < 16; kk++) {
            float a[8], w[8];
            float4 a0 = *(const float4*)&As[kk][ty * 8];
            float4 a1 = *(const float4*)&As[kk][ty * 8 + 4];
            float4 w0 = *(const float4*)&Ws[kk][tx * 8];
            float4 w1 = *(const float4*)&Ws[kk][tx * 8 + 4];
            a[0]=a0.x; a[1]=a0.y; a[2]=a0.z; a[3]=a0.w;
            a[4]=a1.x; a[5]=a1.y; a[6]=a1.z; a[7]=a1.w;
            w[0]=w0.x; w[1]=w0.y; w[2]=w0.z; w[3]=w0.w;
            w[4]=w1.x; w[5]=w1.y; w[6]=w1.z; w[7]=w1.w;
#pragma unroll
            for (int i = 0; i < 8; i++)
#pragma unroll
                for (int j = 0; j < 8; j++)
                    acc[i][j] += a[i] * w[j];
        }
        __syncthreads();
    }

    float bj[8];
#pragma unroll
    for (int j = 0; j < 8; j++) bj[j] = bias[n0 + tx * 8 + j];

    if (mode == 0) {
#pragma unroll
        for (int i = 0; i < 8; i++) {
            float* cp = C0 + (size_t)(m0 + ty * 8 + i) * DIM_ + n0 + tx * 8;
            float4 v0 = make_float4(acc[i][0] + bj[0], acc[i][1] + bj[1],
                                    acc[i][2] + bj[2], acc[i][3] + bj[3]);
            float4 v1 = make_float4(acc[i][4] + bj[4], acc[i][5] + bj[5],
                                    acc[i][6] + bj[6], acc[i][7] + bj[7]);
            ((float4*)cp)[0] = v0;
            ((float4*)cp)[1] = v1;
        }
    } else {
        int nb  = n0 + tx * 8;              // 0..504, never crosses 256 inside a thread
        float* base = (nb < 256) ? C0 : C1;
        int col = nb & 255;
        int h = col >> 5, d = col & 31;     // d in {0,8,16,24}
#pragma unroll
        for (int i = 0; i < 8; i++) {
            int m = m0 + ty * 8 + i;
            int b = m >> 13, t = m & (T_ - 1);
            size_t o = ((size_t)(b * H_ + h) * T_ + t) * HD_ + d;
            float4 v0 = make_float4(acc[i][0] + bj[0], acc[i][1] + bj[1],
                                    acc[i][2] + bj[2], acc[i][3] + bj[3]);
            float4 v1 = make_float4(acc[i][4] + bj[4], acc[i][5] + bj[5],
                                    acc[i][6] + bj[6], acc[i][7] + bj[7]);
            ((float4*)(base + o))[0] = v0;
            ((float4*)(base + o))[1] = v1;
        }
    }
}

// ---------------------------------------------------------------------------
// Flash attention, fp32.
// Grid: (Lq/64, H, B). 256 threads. Thread = (query ql = tid>>2, dim-group g = tid&3).
// Q row (32 floats, pre-scaled) held in registers for the whole kernel.
// K smem tile uses a per-16-row float4 rotation so the 4 g-lanes of a query
// hit distinct bank-quads (conflict-free + 8-way broadcast across q-lanes).
// ---------------------------------------------------------------------------
__global__ __launch_bounds__(256) void attn_kernel()
{
    __shared__ float4 K4[64 * 8];       // 8 KB, swizzled: row t, chunk ((c + (t>>4)) & 7)
    __shared__ float4 V4[64 * 8];       // 8 KB, straight: [t][8 float4]
    __shared__ float  Ps[64][68];       // 17 KB, stride 68 = odd*4 (conflict-free)

    const int tid = threadIdx.x;
    const int ql = tid >> 2;            // 0..63
    const int g  = tid & 3;             // 0..3
    const int qb = blockIdx.x;
    const int h  = blockIdx.y;
    const int b  = blockIdx.z;
    const int qg = (qb << 6) + ql;      // global query index
    const int tb = g << 4;              // this thread's t offset within the 64-chunk

    // Q row into registers, pre-scaled by 1/sqrt(HD)
    const float scale = 0.17677669529663688f;
    float qr[32];
    {
        const float4* qp = (const float4*)(g_Q + ((size_t)(b * LQ_ + qg) * DIM_ + h * HD_));
#pragma unroll
        for (int c = 0; c < 8; c++) {
            float4 v = qp[c];
            qr[c*4+0] = v.x * scale; qr[c*4+1] = v.y * scale;
            qr[c*4+2] = v.z * scale; qr[c*4+3] = v.w * scale;
        }
    }

    float o[8];
#pragma unroll
    for (int i = 0; i < 8; i++) o[i] = 0.f;
    float m = -1e30f, l = 0.f;

    const float4* Kg = (const float4*)(g_K + (size_t)(b * H_ + h) * T_ * HD_);
    const float4* Vg = (const float4*)(g_V + (size_t)(b * H_ + h) * T_ * HD_);
    const float*  mrow = g_mask + (size_t)qg * T_ + tb;

    for (int t0 = 0; t0 < T_; t0 += 64) {
        // --- cooperative K/V tile load (2 float4 each per thread, coalesced) ---
        {
            const float4* Ksrc = Kg + t0 * 8;
            const float4* Vsrc = Vg + t0 * 8;
            int i0 = tid, i1 = tid + 256;
            float4 k0 = Ksrc[i0], k1 = Ksrc[i1];
            int ta = i0 >> 3, ca = i0 & 7;
            K4[ta * 8 + ((ca + (ta >> 4)) & 7)] = k0;
            int tc = i1 >> 3, cc = i1 & 7;
            K4[tc * 8 + ((cc + (tc >> 4)) & 7)] = k1;
            V4[i0] = Vsrc[i0];
            V4[i1] = Vsrc[i1];
        }
        __syncthreads();

        // --- mask values for this thread's 16 keys ---
        float mk[16];
        {
            const float4* mp = (const float4*)(mrow + t0);
#pragma unroll
            for (int j4 = 0; j4 < 4; j4++) {
                float4 v = mp[j4];
                mk[j4*4+0] = v.x; mk[j4*4+1] = v.y;
                mk[j4*4+2] = v.z; mk[j4*4+3] = v.w;
            }
        }

        // --- scores for t in [tb, tb+16) ---
        float s[16];
        float cmax = -1e30f;
#pragma unroll
        for (int j = 0; j < 16; j++) {
            int t = tb + j;                     // t>>4 == g for these t
            float a0 = 0.f, a1 = 0.f, a2 = 0.f, a3 = 0.f;
#pragma unroll
            for (int c = 0; c < 8; c++) {
                float4 kv = K4[t * 8 + ((c + g) & 7)];
                a0 += qr[c*4+0] * kv.x;
                a1 += qr[c*4+1] * kv.y;
                a2 += qr[c*4+2] * kv.z;
                a3 += qr[c*4+3] * kv.w;
            }
            float sv = (a0 + a1) + (a2 + a3) + mk[j];
            s[j] = sv;
            cmax = fmaxf(cmax, sv);
        }
        // reduce max across the 4 lanes of this query (consecutive lanes)
        cmax = fmaxf(cmax, __shfl_xor_sync(0xffffffffu, cmax, 1));
        cmax = fmaxf(cmax, __shfl_xor_sync(0xffffffffu, cmax, 2));

        float newm = fmaxf(m, cmax);
        float alpha = __expf(m - newm);
        m = newm;

        float psum = 0.f;
        float p[16];
#pragma unroll
        for (int j = 0; j < 16; j++) {
            p[j] = __expf(s[j] - newm);
            psum += p[j];
        }
        l = l * alpha + psum;
#pragma unroll
        for (int i = 0; i < 8; i++) o[i] *= alpha;

        // --- publish p tile ---
        {
            float4* prow = (float4*)&Ps[ql][tb];
            prow[0] = make_float4(p[0],  p[1],  p[2],  p[3]);
            prow[1] = make_float4(p[4],  p[5],  p[6],  p[7]);
            prow[2] = make_float4(p[8],  p[9],  p[10], p[11]);
            prow[3] = make_float4(p[12], p[13], p[14], p[15]);
        }
        __syncthreads();

        // --- O += P @ V for this thread's 8 dims, all 64 keys ---
        {
            const float4* pr = (const float4*)&Ps[ql][0];
#pragma unroll
            for (int j4 = 0; j4 < 16; j4++) {
                float4 pv = pr[j4];
                int t = j4 * 4;
                float pe[4] = {pv.x, pv.y, pv.z, pv.w};
#pragma unroll
                for (int e = 0; e < 4; e++) {
                    float4 v0 = V4[(t + e) * 8 + g * 2];
                    float4 v1 = V4[(t + e) * 8 + g * 2 + 1];
                    float w = pe[e];
                    o[0] += w * v0.x; o[1] += w * v0.y;
                    o[2] += w * v0.z; o[3] += w * v0.w;
                    o[4] += w * v1.x; o[5] += w * v1.y;
                    o[6] += w * v1.z; o[7] += w * v1.w;
                }
            }
        }
        __syncthreads();   // before next chunk overwrites K4/V4/Ps
    }

    // combine l across the 4 lanes of this query (all lanes shared the same m history)
    l += __shfl_xor_sync(0xffffffffu, l, 1);
    l += __shfl_xor_sync(0xffffffffu, l, 2);
    float inv = 1.0f / l;

    float* op = g_att + (size_t)(b * LQ_ + qg) * DIM_ + h * HD_ + g * 8;
    ((float4*)op)[0] = make_float4(o[0]*inv, o[1]*inv, o[2]*inv, o[3]*inv);
    ((float4*)op)[1] = make_float4(o[4]*inv, o[5]*inv, o[6]*inv, o[7]*inv);
}

// ---------------------------------------------------------------------------
// Launch
// ---------------------------------------------------------------------------
extern "C" void kernel_launch(void* const* d_in, const int* in_sizes, int n_in,
                              void* d_out, int out_size)
{
    const float* q_in       = (const float*)d_in[0];   // [8,512,256]
    const float* kv_in      = (const float*)d_in[1];   // [8,8192,256]
    const float* w_in       = (const float*)d_in[2];   // [768,256]
    const float* b_in       = (const float*)d_in[3];   // [768]
    const float* w_out      = (const float*)d_in[4];   // [256,256]
    const float* b_out      = (const float*)d_in[5];   // [256]
    const float* rel_bias   = (const float*)d_in[6];   // [257]
    const float* mask_scale = (const float*)d_in[7];   // [1]
    float* out = (float*)d_out;                        // [8,512,256]

    float *gQ, *gK, *gV, *gAtt;
    cudaGetSymbolAddress((void**)&gQ,   g_Q);
    cudaGetSymbolAddress((void**)&gK,   g_K);
    cudaGetSymbolAddress((void**)&gV,   g_V);
    cudaGetSymbolAddress((void**)&gAtt, g_att);

    // 1. mask precompute  [512,8192]
    mask_kernel<<<(LQ_ * T_) / 256, 256>>>(rel_bias, mask_scale);

    // 2. Q projection: [4096,256] @ wq^T  -> g_Q (row-major)
    gemm128<<<dim3(2, 32), 256>>>(q_in, w_in, b_in, gQ, nullptr, 0);

    // 3. K+V projection: [65536,256] @ [wk;wv]^T -> g_K / g_V (head-major)
    gemm128<<<dim3(4, 512), 256>>>(kv_in, w_in + 256 * 256, b_in + 256, gK, gV, 1);

    // 4. attention
    attn_kernel<<<dim3(LQ_ / 64, H_, B_), 256>>>();

    // 5. output projection: [4096,256] @ out_proj_w^T + b -> d_out
    gemm128<<<dim3(2, 32), 256>>>(gAtt, w_out, b_out, out, nullptr, 0);
}

// round 9
// speedup vs baseline: 1.7324x; 1.7324x over previous
#include <cuda_runtime.h>
#include <math.h>

// Problem constants
#define B_   8
#define LQ_  512
#define T_   8192
#define DIM_ 256
#define H_   8
#define HD_  32

// ---------------------------------------------------------------------------
// Scratch (device globals: allocation-free per harness rules)
// ---------------------------------------------------------------------------
__device__ float g_Q[(size_t)B_ * LQ_ * DIM_];              //  4 MB, [b][q][256]
__device__ float g_K[(size_t)B_ * H_ * HD_ * T_];           // 64 MB, TRANSPOSED [b][h][d][t]
__device__ float g_V[(size_t)B_ * H_ * T_ * HD_];           // 64 MB, [b][h][t][d]
__device__ float g_mask[(size_t)LQ_ * T_];                  // 16 MB, [q][t]
__device__ float g_att[(size_t)B_ * LQ_ * DIM_];            //  4 MB, [b][q][h*32+d]

// ---------------------------------------------------------------------------
// f32x2 packed helpers (Blackwell): 2 fp32 FMA per instruction, exact fp32.
// ---------------------------------------------------------------------------
__device__ __forceinline__ unsigned long long dup2(float x) {
    unsigned long long r;
    asm("mov.b64 %0, {%1, %1};" : "=l"(r) : "f"(x));
    return r;
}
__device__ __forceinline__ unsigned long long pack2(float lo, float hi) {
    unsigned long long r;
    asm("mov.b64 %0, {%1, %2};" : "=l"(r) : "f"(lo), "f"(hi));
    return r;
}
__device__ __forceinline__ void unpack2(float& lo, float& hi, unsigned long long v) {
    asm("mov.b64 {%0, %1}, %2;" : "=f"(lo), "=f"(hi) : "l"(v));
}
__device__ __forceinline__ void ffma2(unsigned long long& acc,
                                      unsigned long long a, unsigned long long b) {
    asm("fma.rn.f32x2 %0, %1, %2, %0;" : "+l"(acc) : "l"(a), "l"(b));
}
__device__ __forceinline__ void fmul2(unsigned long long& acc, unsigned long long a) {
    asm("mul.rn.f32x2 %0, %0, %1;" : "+l"(acc) : "l"(a));
}

// ---------------------------------------------------------------------------
// Mask precompute
// ---------------------------------------------------------------------------
__global__ void mask_kernel(const float* __restrict__ rel_bias,
                            const float* __restrict__ mask_scale)
{
    int idx = blockIdx.x * 256 + threadIdx.x;
    int q = idx >> 13;
    int t = idx & (T_ - 1);
    const float step = 8191.0f / 511.0f;
    float tau = (float)q * step;
    float dt = (float)t - tau;
    float dtc = fminf(fmaxf(dt, -128.0f), 128.0f);
    int bi = (int)dtc + 128;
    float bias = rel_bias[bi];
    float z = dt * (1.0f / 64.0f);
    float lg = logf(expf(-0.5f * z * z) + 1e-6f);
    g_mask[idx] = mask_scale[0] * (bias + lg);
}

// ---------------------------------------------------------------------------
// fp32 GEMM with f32x2 packed FMA:  C[m][n] = sum_k A[m][k]*W[n][k] + bias
// CTA 128x128, 256 threads, 8x8 micro-tile (as 4 row-pairs x 8 cols), k-chunk 16.
// mode 0: row-major C0 (ld=256), bias per column n
// mode 1: V head-major store: row m = token, col n = h*32+d, bias per column
// mode 2: K transposed store: row m = output dim (bias per ROW), col n = token;
//         C0 layout [b][h][d][t]
// ---------------------------------------------------------------------------
__global__ __launch_bounds__(256) void gemm128(
    const float* __restrict__ A, const float* __restrict__ W,
    const float* __restrict__ bias,
    float* __restrict__ C0, int mode)
{
    __shared__ __align__(16) float As[16][132];
    __shared__ __align__(16) float Ws[16][132];

    const int tid = threadIdx.x;
    const int tx = tid & 15;
    const int ty = tid >> 4;
    const int m0 = blockIdx.y << 7;
    const int n0 = blockIdx.x << 7;

    unsigned long long acc2[4][8];   // [row-pair][col]
#pragma unroll
    for (int ip = 0; ip < 4; ip++)
#pragma unroll
        for (int j = 0; j < 8; j++) acc2[ip][j] = 0ull;

    const int lr = tid >> 2;
    const int lk = (tid & 3) << 2;

    for (int kc = 0; kc < 256; kc += 16) {
#pragma unroll
        for (int p = 0; p < 2; p++) {
            int r = lr + (p << 6);
            float4 av = *(const float4*)(A + (size_t)(m0 + r) * DIM_ + kc + lk);
            As[lk + 0][r] = av.x; As[lk + 1][r] = av.y;
            As[lk + 2][r] = av.z; As[lk + 3][r] = av.w;
            float4 wv = *(const float4*)(W + (size_t)(n0 + r) * DIM_ + kc + lk);
            Ws[lk + 0][r] = wv.x; Ws[lk + 1][r] = wv.y;
            Ws[lk + 2][r] = wv.z; Ws[lk + 3][r] = wv.w;
        }
        __syncthreads();
#pragma unroll
        for (int kk = 0; kk < 16; kk++) {
            ulonglong2 a01 = *(const ulonglong2*)&As[kk][ty * 8];
            ulonglong2 a23 = *(const ulonglong2*)&As[kk][ty * 8 + 4];
            float4 w0 = *(const float4*)&Ws[kk][tx * 8];
            float4 w1 = *(const float4*)&Ws[kk][tx * 8 + 4];
            unsigned long long wd[8];
            wd[0] = dup2(w0.x); wd[1] = dup2(w0.y); wd[2] = dup2(w0.z); wd[3] = dup2(w0.w);
            wd[4] = dup2(w1.x); wd[5] = dup2(w1.y); wd[6] = dup2(w1.z); wd[7] = dup2(w1.w);
            unsigned long long ap[4] = {a01.x, a01.y, a23.x, a23.y};
#pragma unroll
            for (int ip = 0; ip < 4; ip++)
#pragma unroll
                for (int j = 0; j < 8; j++)
                    ffma2(acc2[ip][j], ap[ip], wd[j]);
        }
        __syncthreads();
    }

    // unpack to scalar 8x8
    float C[8][8];
#pragma unroll
    for (int ip = 0; ip < 4; ip++)
#pragma unroll
        for (int j = 0; j < 8; j++)
            unpack2(C[2 * ip][j], C[2 * ip + 1][j], acc2[ip][j]);

    if (mode == 2) {
        // bias per ROW (output dim), transposed store into [b][h][d][t]
        float br[8];
#pragma unroll
        for (int i = 0; i < 8; i++) br[i] = bias[m0 + ty * 8 + i];
        int n = n0 + tx * 8;                 // token base, 8 consecutive
        int bb = n >> 13, t = n & (T_ - 1);
#pragma unroll
        for (int i = 0; i < 8; i++) {
            int r = m0 + ty * 8 + i;         // 0..255
            int h = r >> 5, d = r & 31;
            float* cp = C0 + (((size_t)((bb * H_ + h) * HD_ + d)) << 13) + t;
            ((float4*)cp)[0] = make_float4(C[i][0] + br[i], C[i][1] + br[i],
                                           C[i][2] + br[i], C[i][3] + br[i]);
            ((float4*)cp)[1] = make_float4(C[i][4] + br[i], C[i][5] + br[i],
                                           C[i][6] + br[i], C[i][7] + br[i]);
        }
        return;
    }

    float bj[8];
#pragma unroll
    for (int j = 0; j < 8; j++) bj[j] = bias[n0 + tx * 8 + j];

    if (mode == 0) {
#pragma unroll
        for (int i = 0; i < 8; i++) {
            float* cp = C0 + (size_t)(m0 + ty * 8 + i) * DIM_ + n0 + tx * 8;
            ((float4*)cp)[0] = make_float4(C[i][0] + bj[0], C[i][1] + bj[1],
                                           C[i][2] + bj[2], C[i][3] + bj[3]);
            ((float4*)cp)[1] = make_float4(C[i][4] + bj[4], C[i][5] + bj[5],
                                           C[i][6] + bj[6], C[i][7] + bj[7]);
        }
    } else {
        // mode 1: V natural head-major [b][h][t][d]
        int n = n0 + tx * 8;                 // dim base (0..255)
        int h = n >> 5, d = n & 31;
#pragma unroll
        for (int i = 0; i < 8; i++) {
            int m = m0 + ty * 8 + i;
            int b = m >> 13, t = m & (T_ - 1);
            float* cp = C0 + ((size_t)((b * H_ + h) * T_ + t)) * HD_ + d;
            ((float4*)cp)[0] = make_float4(C[i][0] + bj[0], C[i][1] + bj[1],
                                           C[i][2] + bj[2], C[i][3] + bj[3]);
            ((float4*)cp)[1] = make_float4(C[i][4] + bj[4], C[i][5] + bj[5],
                                           C[i][6] + bj[6], C[i][7] + bj[7]);
        }
    }
}

// ---------------------------------------------------------------------------
// Flash attention, fp32 + f32x2 packed FMA, GEMM-style micro-tiles.
// Grid (Lq/64, H, B), 256 threads: tx = tid&15, ty = tid>>4.
// QK: thread computes 4q x 4k (q = 4ty.., k = 4tx..) reading Qs[d][q], Ks[d][k].
// PV: thread owns 4q x 2d (d = 2tx..) reading Pt[k][q] pairs, Vs[k][d] pairs.
// K comes pre-transposed from gmem ([b][h][d][t]) -> no smem transpose needed.
// ---------------------------------------------------------------------------
__global__ __launch_bounds__(256, 2) void attn_kernel()
{
    __shared__ __align__(16) float Qs[32 * 72];   // [d][q], pad 72
    __shared__ __align__(16) float Ks[32 * 72];   // [d][t], pad 72
    __shared__ __align__(16) float Vsf[64 * 32];  // [t][d] natural
    __shared__ __align__(16) float Pt[64 * 68];   // [k][q-group swizzled], pad 68

    const int tid = threadIdx.x;
    const int tx = tid & 15;
    const int ty = tid >> 4;
    const int qb = blockIdx.x;
    const int h  = blockIdx.y;
    const int b  = blockIdx.z;
    const int qg0 = qb << 6;

    const float scale = 0.17677669529663688f;   // 1/sqrt(32)

    const float* Ktg = g_K + (size_t)(b * H_ + h) * HD_ * T_;   // [d][t]
    const float4* Vtg4 = (const float4*)(g_V + (size_t)(b * H_ + h) * T_ * HD_);

    // ---- fill Qs[d][q] (transposed, pre-scaled), once per CTA ----
#pragma unroll
    for (int r = 0; r < 2; r++) {
        int i = tid + r * 256;          // 0..511
        int q = i >> 3;                 // 0..63
        int c4 = i & 7;                 // dim float4 group
        float4 v = *(const float4*)(g_Q + ((size_t)(b * LQ_ + qg0 + q) * DIM_ + h * HD_ + c4 * 4));
        Qs[(4 * c4 + 0) * 72 + q] = v.x * scale;
        Qs[(4 * c4 + 1) * 72 + q] = v.y * scale;
        Qs[(4 * c4 + 2) * 72 + q] = v.z * scale;
        Qs[(4 * c4 + 3) * 72 + q] = v.w * scale;
    }

    // per-thread state
    unsigned long long oacc[2][2];      // [q-pair][dim]
    oacc[0][0] = oacc[0][1] = oacc[1][0] = oacc[1][1] = 0ull;
    float mreg[4], lreg[4];
#pragma unroll
    for (int i = 0; i < 4; i++) { mreg[i] = -1e30f; lreg[i] = 0.f; }

    // loader indices
    const int dK = tid >> 4;            // 0..15 (+16 second half)
    const int cK = tid & 15;            // float4 col within 64-key chunk

    // mask row pointers for this thread's 4 queries
    const float* mrow0 = g_mask + (size_t)(qg0 + 4 * ty + 0) * T_;
    const float* mrow1 = g_mask + (size_t)(qg0 + 4 * ty + 1) * T_;
    const float* mrow2 = g_mask + (size_t)(qg0 + 4 * ty + 2) * T_;
    const float* mrow3 = g_mask + (size_t)(qg0 + 4 * ty + 3) * T_;

    // preload chunk 0 into registers
    float4 kreg[2], vreg[2];
#pragma unroll
    for (int r = 0; r < 2; r++) {
        kreg[r] = *(const float4*)(Ktg + (size_t)(dK + r * 16) * T_ + cK * 4);
        vreg[r] = Vtg4[tid + r * 256];
    }

    for (int t0 = 0; t0 < T_; t0 += 64) {
        // ---- commit prefetched chunk to smem ----
#pragma unroll
        for (int r = 0; r < 2; r++) {
            *(float4*)&Ks[(dK + r * 16) * 72 + cK * 4] = kreg[r];
            ((float4*)Vsf)[tid + r * 256] = vreg[r];
        }
        __syncthreads();

        // ---- prefetch next chunk (overlaps with compute) ----
        if (t0 + 64 < T_) {
#pragma unroll
            for (int r = 0; r < 2; r++) {
                kreg[r] = *(const float4*)(Ktg + (size_t)(dK + r * 16) * T_ + (t0 + 64) + cK * 4);
                vreg[r] = Vtg4[(t0 + 64) * 8 + tid + r * 256];
            }
        }

        // mask values for 4q x 4k (issued early to hide latency)
        float4 mk0 = *(const float4*)(mrow0 + t0 + 4 * tx);
        float4 mk1 = *(const float4*)(mrow1 + t0 + 4 * tx);
        float4 mk2 = *(const float4*)(mrow2 + t0 + 4 * tx);
        float4 mk3 = *(const float4*)(mrow3 + t0 + 4 * tx);

        // ---- QK: acc[i][kp] (q = 4ty+i, keys (4tx+2kp, +1)) ----
        unsigned long long acc[4][2];
#pragma unroll
        for (int i = 0; i < 4; i++) { acc[i][0] = 0ull; acc[i][1] = 0ull; }

        const float* qcol = Qs + 4 * ty;
        const float* kcol = Ks + 4 * tx;
#pragma unroll
        for (int d = 0; d < 32; d++) {
            float4 qv = *(const float4*)(qcol + d * 72);
            ulonglong2 kv = *(const ulonglong2*)(kcol + d * 72);
            unsigned long long q0 = dup2(qv.x), q1 = dup2(qv.y),
                               q2 = dup2(qv.z), q3 = dup2(qv.w);
            ffma2(acc[0][0], q0, kv.x); ffma2(acc[0][1], q0, kv.y);
            ffma2(acc[1][0], q1, kv.x); ffma2(acc[1][1], q1, kv.y);
            ffma2(acc[2][0], q2, kv.x); ffma2(acc[2][1], q2, kv.y);
            ffma2(acc[3][0], q3, kv.x); ffma2(acc[3][1], q3, kv.y);
        }

        float s[4][4];
#pragma unroll
        for (int i = 0; i < 4; i++) {
            unpack2(s[i][0], s[i][1], acc[i][0]);
            unpack2(s[i][2], s[i][3], acc[i][1]);
        }
        s[0][0] += mk0.x; s[0][1] += mk0.y; s[0][2] += mk0.z; s[0][3] += mk0.w;
        s[1][0] += mk1.x; s[1][1] += mk1.y; s[1][2] += mk1.z; s[1][3] += mk1.w;
        s[2][0] += mk2.x; s[2][1] += mk2.y; s[2][2] += mk2.z; s[2][3] += mk2.w;
        s[3][0] += mk3.x; s[3][1] += mk3.y; s[3][2] += mk3.z; s[3][3] += mk3.w;

        // ---- online softmax (per q row; reduce across 16 tx lanes) ----
        float alpha[4];
#pragma unroll
        for (int i = 0; i < 4; i++) {
            float rm = fmaxf(fmaxf(s[i][0], s[i][1]), fmaxf(s[i][2], s[i][3]));
            rm = fmaxf(rm, __shfl_xor_sync(0xffffffffu, rm, 1));
            rm = fmaxf(rm, __shfl_xor_sync(0xffffffffu, rm, 2));
            rm = fmaxf(rm, __shfl_xor_sync(0xffffffffu, rm, 4));
            rm = fmaxf(rm, __shfl_xor_sync(0xffffffffu, rm, 8));
            float nm = fmaxf(mreg[i], rm);
            float al = __expf(mreg[i] - nm);
            mreg[i] = nm;
            float rs = 0.f;
#pragma unroll
            for (int k = 0; k < 4; k++) {
                float p = __expf(s[i][k] - nm);
                s[i][k] = p;
                rs += p;
            }
            rs += __shfl_xor_sync(0xffffffffu, rs, 1);
            rs += __shfl_xor_sync(0xffffffffu, rs, 2);
            rs += __shfl_xor_sync(0xffffffffu, rs, 4);
            rs += __shfl_xor_sync(0xffffffffu, rs, 8);
            lreg[i] = lreg[i] * al + rs;
            alpha[i] = al;
        }
        {
            unsigned long long ap0 = pack2(alpha[0], alpha[1]);
            unsigned long long ap1 = pack2(alpha[2], alpha[3]);
            fmul2(oacc[0][0], ap0); fmul2(oacc[0][1], ap0);
            fmul2(oacc[1][0], ap1); fmul2(oacc[1][1], ap1);
        }

        // ---- publish P transposed: Pt[k][4 * ((ty + k/4)&15) ..] ----
#pragma unroll
        for (int kk = 0; kk < 4; kk++) {
            int k = 4 * tx + kk;
            int cg = (ty + tx) & 15;     // (ty + (k>>2)) & 15
            *(float4*)&Pt[k * 68 + 4 * cg] =
                make_float4(s[0][kk], s[1][kk], s[2][kk], s[3][kk]);
        }
        __syncthreads();

        // ---- PV: oacc[qp][dj] += p-pair * dup(v) over 64 keys ----
        {
            const float* vp = Vsf + 2 * tx;
#pragma unroll 8
            for (int k = 0; k < 64; k++) {
                int cg = (ty + (k >> 2)) & 15;
                ulonglong2 pp = *(const ulonglong2*)&Pt[k * 68 + 4 * cg];
                float2 vv = *(const float2*)(vp + k * 32);
                unsigned long long v0 = dup2(vv.x), v1 = dup2(vv.y);
                ffma2(oacc[0][0], pp.x, v0); ffma2(oacc[0][1], pp.x, v1);
                ffma2(oacc[1][0], pp.y, v0); ffma2(oacc[1][1], pp.y, v1);
            }
        }
        __syncthreads();   // protect Ks/Vsf/Pt before next iteration
    }

    // ---- finalize: divide by l, write out ----
    float of[4][2];
    unpack2(of[0][0], of[1][0], oacc[0][0]);
    unpack2(of[0][1], of[1][1], oacc[0][1]);
    unpack2(of[2][0], of[3][0], oacc[1][0]);
    unpack2(of[2][1], of[3][1], oacc[1][1]);

    float* ob = g_att + (size_t)(b * LQ_ + qg0 + 4 * ty) * DIM_ + h * HD_ + 2 * tx;
#pragma unroll
    for (int i = 0; i < 4; i++) {
        float inv = 1.0f / lreg[i];
        *(float2*)(ob + (size_t)i * DIM_) = make_float2(of[i][0] * inv, of[i][1] * inv);
    }
}

// ---------------------------------------------------------------------------
// Launch
// ---------------------------------------------------------------------------
extern "C" void kernel_launch(void* const* d_in, const int* in_sizes, int n_in,
                              void* d_out, int out_size)
{
    const float* q_in       = (const float*)d_in[0];   // [8,512,256]
    const float* kv_in      = (const float*)d_in[1];   // [8,8192,256]
    const float* w_in       = (const float*)d_in[2];   // [768,256]
    const float* b_in       = (const float*)d_in[3];   // [768]
    const float* w_out      = (const float*)d_in[4];   // [256,256]
    const float* b_out      = (const float*)d_in[5];   // [256]
    const float* rel_bias   = (const float*)d_in[6];   // [257]
    const float* mask_scale = (const float*)d_in[7];   // [1]
    float* out = (float*)d_out;                        // [8,512,256]

    float *gQ, *gK, *gV, *gAtt;
    cudaGetSymbolAddress((void**)&gQ,   g_Q);
    cudaGetSymbolAddress((void**)&gK,   g_K);
    cudaGetSymbolAddress((void**)&gV,   g_V);
    cudaGetSymbolAddress((void**)&gAtt, g_att);

    // 1. mask precompute [512,8192]
    mask_kernel<<<(LQ_ * T_) / 256, 256>>>(rel_bias, mask_scale);

    // 2. Q projection: [4096,256] @ wq^T -> g_Q row-major
    gemm128<<<dim3(2, 32), 256>>>(q_in, w_in, b_in, gQ, 0);

    // 3. V projection: [65536,256] @ wv^T -> g_V head-major [b][h][t][d]
    gemm128<<<dim3(2, 512), 256>>>(kv_in, w_in + 2 * 256 * 256, b_in + 512, gV, 1);

    // 4. K projection, transposed orientation: C[dim][token] -> g_K [b][h][d][t]
    gemm128<<<dim3(512, 2), 256>>>(w_in + 256 * 256, kv_in, b_in + 256, gK, 2);

    // 5. attention
    attn_kernel<<<dim3(LQ_ / 64, H_, B_), 256>>>();

    // 6. output projection
    gemm128<<<dim3(2, 32), 256>>>(gAtt, w_out, b_out, out, 0);
}